// round 7
// baseline (speedup 1.0000x reference)
#include <cuda_runtime.h>
#include <math.h>

#define BDIM   16
#define TDIM   2048
#define FDIM   128
#define LDIM   16
#define LIB    1016
#define NROWS  (BDIM*TDIM)          // 32768

// output offsets (floats)
#define Y_OFF   ((size_t)0)
#define X_OFF   ((size_t)524288)
#define Z_OFF   ((size_t)4718592)
#define J_OFF   ((size_t)5242880)
#define WS_OFF  ((size_t)72351744)
#define WD_OFF  ((size_t)72368000)

// jac float4 region split:  encoder [0,2M) | hilbert [2M,6.29M) | fused [6.29M,16.77M)
#define JAC_TOTAL4   ((size_t)16777216)
#define JAC_E_BEG    ((size_t)0)
#define JAC_E_LEN    ((size_t)2097152)
#define JAC_H_BEG    ((size_t)2097152)
#define JAC_H_LEN    ((size_t)4194304)
#define JAC_F_BEG    ((size_t)6291456)
#define JAC_F_LEN    ((size_t)10485760)

// scratch: hilbert I/O in [B,L,T] layout (coalesced), transposed W_sindy
__device__ float g_amp[BDIM*LDIM*TDIM];
__device__ float g_ang[BDIM*LDIM*TDIM];
__device__ float g_zt [BDIM*LDIM*TDIM];
__device__ __align__(16) float g_Wt[LIB*LDIM];   // [d][l]

// ---------------------------------------------------------------------------
// jac streaming store helper: writes tile-repeat into a float4 sub-region
// ---------------------------------------------------------------------------
__device__ __forceinline__ void jac_store(float* __restrict__ out,
                                          const float4* __restrict__ tile,
                                          size_t region_beg, size_t region_len,
                                          int jb, int nblk, int tid, int nthr)
{
    float4* jac4 = (float4*)(out + J_OFF);
    const size_t stride = (size_t)nblk * nthr;
    for (size_t v = (size_t)jb * nthr + tid; v < region_len; v += stride) {
        size_t gidx = region_beg + v;
        __stcs(&jac4[gidx], tile[gidx & 511]);
    }
}

// ---------------------------------------------------------------------------
// K1: encoder. blocks [0,256): z = x @ W_enc^T + b_enc, 2 threads per row.
//     block 256: transpose W_sindy -> g_Wt.
//     blocks [257,769): jac region E.
// ---------------------------------------------------------------------------
__global__ __launch_bounds__(256) void encoder_kernel(
    const float* __restrict__ x, const float* __restrict__ W_enc,
    const float* __restrict__ b_enc, const float* __restrict__ W_sindy,
    float* __restrict__ z_out, float* __restrict__ out)
{
    __shared__ float4 sW[512];   // W_enc [16][128] as float4[16][32]
    __shared__ float  sb[16];
    const int tid = threadIdx.x;
    const int bb  = blockIdx.x;

    if (bb == 256) {
        // transpose W_sindy [16][1016] -> g_Wt [1016][16]
        for (int i = tid; i < LDIM * LIB; i += 256) {
            int l = i / LIB;
            int d = i - l * LIB;
            g_Wt[d * 16 + l] = W_sindy[i];
        }
        return;
    }

    for (int i = tid; i < 512; i += 256) sW[i] = ((const float4*)W_enc)[i];

    if (bb >= 257) {
        __syncthreads();
        jac_store(out, sW, JAC_E_BEG, JAC_E_LEN, bb - 257, 512, tid, 256);
        return;
    }

    if (tid < 16) sb[tid] = b_enc[tid];
    __syncthreads();

    const int gt   = bb * 256 + tid;
    const int row  = gt >> 1;
    const int half = gt & 1;
    const float4* xr = (const float4*)(x + (size_t)row * FDIM) + half * 16;

    float acc[16];
#pragma unroll
    for (int l = 0; l < 16; l++) acc[l] = 0.0f;

#pragma unroll
    for (int c = 0; c < 16; c++) {
        float4 xv = xr[c];
#pragma unroll
        for (int l = 0; l < 16; l++) {
            float4 wv = sW[l * 32 + half * 16 + c];
            acc[l] = fmaf(xv.x, wv.x, acc[l]);
            acc[l] = fmaf(xv.y, wv.y, acc[l]);
            acc[l] = fmaf(xv.z, wv.z, acc[l]);
            acc[l] = fmaf(xv.w, wv.w, acc[l]);
        }
    }
#pragma unroll
    for (int l = 0; l < 16; l++)
        acc[l] += __shfl_xor_sync(0xffffffffu, acc[l], 1);
#pragma unroll
    for (int l = 0; l < 16; l++) acc[l] += sb[l];

    float4* zo = (float4*)(z_out + (size_t)row * LDIM);
    if (half == 0) {
        zo[0] = make_float4(acc[0], acc[1], acc[2],  acc[3]);
        zo[1] = make_float4(acc[4], acc[5], acc[6],  acc[7]);
    } else {
        zo[2] = make_float4(acc[8],  acc[9],  acc[10], acc[11]);
        zo[3] = make_float4(acc[12], acc[13], acc[14], acc[15]);
    }
    // transposed copy for hilbert: [B,L,T]
    const int b = row >> 11;
    const int t = row & 2047;
#pragma unroll
    for (int k = 0; k < 8; k++) {
        int l = half * 8 + k;
        g_zt[((size_t)(b * 16 + l)) * TDIM + t] = acc[l];
    }
}

// ---------------------------------------------------------------------------
// K2: hilbert. blocks [0,256): one 2048-pt fwd FFT + filter + inv FFT per
//     (b,lat) sequence, I/O in [B,L,T] layout (coalesced).
//     blocks [256,768): jac region H.
// ---------------------------------------------------------------------------
__global__ __launch_bounds__(512) void hilbert_kernel(
    const float* __restrict__ W_enc, float* __restrict__ out)
{
    __shared__ float2 bufA[2048];
    __shared__ float2 bufB[2048];
    const int tid = threadIdx.x;
    const int bb  = blockIdx.x;

    if (bb >= 256) {
        float4* tile = (float4*)bufA;
        const float4* we4 = (const float4*)W_enc;
        if (tid < 512) tile[tid] = we4[tid];
        __syncthreads();
        jac_store(out, tile, JAC_H_BEG, JAC_H_LEN, bb - 256, 512, tid, 512);
        return;
    }

    const int seq = bb;  // b*16 + lat
    const float* zp = g_zt + (size_t)seq * TDIM;
    for (int t = tid; t < 2048; t += 512)
        bufA[t] = make_float2(zp[t], 0.0f);
    __syncthreads();

    float2* src = bufA;
    float2* dst = bufB;

    // forward FFT (sign -1), Stockham radix-2
    for (int p = 0; p < 11; p++) {
        const int   len  = 1 << p;
        const float coef = -3.14159265358979323846f / (float)len;
        for (int j = tid; j < 1024; j += 512) {
            const int k = j & (len - 1);
            float2 a  = src[j];
            float2 b2 = src[j + 1024];
            float s, c;
            __sincosf(coef * (float)k, &s, &c);
            float2 wb = make_float2(c * b2.x - s * b2.y, c * b2.y + s * b2.x);
            const int base = 2 * (j - k) + k;
            dst[base]       = make_float2(a.x + wb.x, a.y + wb.y);
            dst[base + len] = make_float2(a.x - wb.x, a.y - wb.y);
        }
        __syncthreads();
        float2* tsw = src; src = dst; dst = tsw;
    }

    // hilbert filter: H[0]=0, H[1..1023]=2, H[1024..2047]=0
    for (int t = tid; t < 2048; t += 512) {
        float h = (t >= 1 && t < 1024) ? 2.0f : 0.0f;
        src[t].x *= h;
        src[t].y *= h;
    }
    __syncthreads();

    // inverse FFT (sign +1)
    for (int p = 0; p < 11; p++) {
        const int   len  = 1 << p;
        const float coef = 3.14159265358979323846f / (float)len;
        for (int j = tid; j < 1024; j += 512) {
            const int k = j & (len - 1);
            float2 a  = src[j];
            float2 b2 = src[j + 1024];
            float s, c;
            __sincosf(coef * (float)k, &s, &c);
            float2 wb = make_float2(c * b2.x - s * b2.y, c * b2.y + s * b2.x);
            const int base = 2 * (j - k) + k;
            dst[base]       = make_float2(a.x + wb.x, a.y + wb.y);
            dst[base + len] = make_float2(a.x - wb.x, a.y - wb.y);
        }
        __syncthreads();
        float2* tsw = src; src = dst; dst = tsw;
    }

    const float scale = 1.0f / 2048.0f;
    const size_t ob = (size_t)seq * TDIM;
    for (int t = tid; t < 2048; t += 512) {
        float re = src[t].x * scale;
        float im = src[t].y * scale;
        g_amp[ob + t] = sqrtf(re * re + im * im);
        g_ang[ob + t] = atan2f(im, re);
    }
}

// ---------------------------------------------------------------------------
// K3: fused. period-7 role interleave: 1 Y : 1 X : 5 J, + 1 copy block.
//   Y: y_hat = theta @ W_sindy^T + b_sindy via packed f32x2 FMA,
//      W read from g_Wt (L1-resident, uniform-address broadcast)
//   X: x_hat = z @ W_dec^T + b_dec
//   J: jac region F (streaming stores)
//   C: copy W_sindy, W_dec
// dynamic smem 25088 B (per-thread feature staging only)
// ---------------------------------------------------------------------------
// NOTE: each FEAT consumes exactly ONE g_Wt row = 16 floats (64 bytes loaded
// via four v2.u64 at byte offsets 0/16/32/48). wp advances by 16 FLOATS.
// (Round-4 bug was `wp += 64` floats = 256B -> walked off g_Wt after 254 feats.)
#define FEAT(val) do {                                                        \
    float fv_ = (val);                                                        \
    unsigned long long pk_;                                                   \
    asm("mov.b64 %0,{%1,%1};" : "=l"(pk_) : "r"(__float_as_uint(fv_)));       \
    unsigned long long w0_,w1_,w2_,w3_,w4_,w5_,w6_,w7_;                       \
    asm("ld.global.nc.v2.u64 {%0,%1},[%2];"    : "=l"(w0_),"=l"(w1_) : "l"(wp)); \
    asm("ld.global.nc.v2.u64 {%0,%1},[%2+16];" : "=l"(w2_),"=l"(w3_) : "l"(wp)); \
    asm("ld.global.nc.v2.u64 {%0,%1},[%2+32];" : "=l"(w4_),"=l"(w5_) : "l"(wp)); \
    asm("ld.global.nc.v2.u64 {%0,%1},[%2+48];" : "=l"(w6_),"=l"(w7_) : "l"(wp)); \
    wp += 16;                                                                 \
    asm("fma.rn.f32x2 %0,%1,%2,%0;" : "+l"(A0) : "l"(pk_), "l"(w0_));         \
    asm("fma.rn.f32x2 %0,%1,%2,%0;" : "+l"(A1) : "l"(pk_), "l"(w1_));         \
    asm("fma.rn.f32x2 %0,%1,%2,%0;" : "+l"(A2) : "l"(pk_), "l"(w2_));         \
    asm("fma.rn.f32x2 %0,%1,%2,%0;" : "+l"(A3) : "l"(pk_), "l"(w3_));         \
    asm("fma.rn.f32x2 %0,%1,%2,%0;" : "+l"(A4) : "l"(pk_), "l"(w4_));         \
    asm("fma.rn.f32x2 %0,%1,%2,%0;" : "+l"(A5) : "l"(pk_), "l"(w5_));         \
    asm("fma.rn.f32x2 %0,%1,%2,%0;" : "+l"(A6) : "l"(pk_), "l"(w6_));         \
    asm("fma.rn.f32x2 %0,%1,%2,%0;" : "+l"(A7) : "l"(pk_), "l"(w7_));         \
} while (0)

__global__ __launch_bounds__(128) void fused_kernel(
    const float* __restrict__ W_enc,
    const float* __restrict__ W_dec,   const float* __restrict__ b_dec,
    const float* __restrict__ W_sindy, const float* __restrict__ b_sindy,
    const float* __restrict__ z,       // z region of output blob [B,T,L]
    float* __restrict__ out)
{
    extern __shared__ float smem[];
    const int tid = threadIdx.x;
    const int bb  = blockIdx.x;

    if (bb == 1792) {
        // ---- role C ----
        const float4* ws4 = (const float4*)W_sindy;
        float4* o1 = (float4*)(out + WS_OFF);
        for (int i = tid; i < (LDIM * LIB) / 4; i += 128) o1[i] = ws4[i];
        const float4* wd4 = (const float4*)W_dec;
        float4* o2 = (float4*)(out + WD_OFF);
        for (int i = tid; i < (FDIM * LDIM) / 4; i += 128) o2[i] = wd4[i];
        return;
    }

    const int g = bb / 7;
    const int r = bb - g * 7;

    if (r == 0) {
        // ---- role Y ----
        const int row = g * 128 + tid;
        const int b   = row >> 11;
        const int t   = row & 2047;
        float* f = smem + tid * 49;

        const float4* zr4 = (const float4*)(z + (size_t)row * LDIM);
        float4 z0 = zr4[0], z1 = zr4[1], z2 = zr4[2], z3 = zr4[3];
        f[0]=z0.x; f[1]=z0.y; f[2]=z0.z; f[3]=z0.w;
        f[4]=z1.x; f[5]=z1.y; f[6]=z1.z; f[7]=z1.w;
        f[8]=z2.x; f[9]=z2.y; f[10]=z2.z; f[11]=z2.w;
        f[12]=z3.x; f[13]=z3.y; f[14]=z3.z; f[15]=z3.w;
#pragma unroll
        for (int i = 0; i < 16; i++) {
            f[16 + i] = g_amp[((size_t)(b * 16 + i)) * TDIM + t];
            f[32 + i] = g_ang[((size_t)(b * 16 + i)) * TDIM + t];
        }

        const unsigned long long* b64 = (const unsigned long long*)b_sindy;
        unsigned long long A0 = b64[0], A1 = b64[1], A2 = b64[2], A3 = b64[3];
        unsigned long long A4 = b64[4], A5 = b64[5], A6 = b64[6], A7 = b64[7];
        const float* wp = g_Wt;

        // degree 1 (16)
#pragma unroll 1
        for (int i = 0; i < 16; i++) FEAT(f[i]);
        // degree 2 (136)
#pragma unroll 1
        for (int i = 0; i < 16; i++) {
            float zi = f[i];
#pragma unroll 1
            for (int j = i; j < 16; j++) FEAT(zi * f[j]);
        }
        // degree 3 (816)
#pragma unroll 1
        for (int i = 0; i < 16; i++) {
            float zi = f[i];
#pragma unroll 1
            for (int j = i; j < 16; j++) {
                float p = zi * f[j];
#pragma unroll 1
                for (int k = j; k < 16; k++) FEAT(p * f[k]);
            }
        }
        // z(16), amp(16), ang(16)
#pragma unroll 1
        for (int i = 0; i < 48; i++) FEAT(f[i]);

        ulonglong2* yo = (ulonglong2*)(out + Y_OFF + (size_t)row * LDIM);
        ulonglong2 q;
        q.x = A0; q.y = A1; yo[0] = q;
        q.x = A2; q.y = A3; yo[1] = q;
        q.x = A4; q.y = A5; yo[2] = q;
        q.x = A6; q.y = A7; yo[3] = q;
    } else if (r == 1) {
        // ---- role X ----
        const float4* wd = (const float4*)W_dec;   // [128][4]
        float4 w0 = wd[tid * 4 + 0];
        float4 w1 = wd[tid * 4 + 1];
        float4 w2 = wd[tid * 4 + 2];
        float4 w3 = wd[tid * 4 + 3];
        float  bd = b_dec[tid];
        const int rbase = g * 128;
#pragma unroll 4
        for (int rr = 0; rr < 128; rr++) {
            const float4* zr = (const float4*)(z + (size_t)(rbase + rr) * LDIM);
            float4 z0 = __ldg(zr + 0), z1 = __ldg(zr + 1);
            float4 z2 = __ldg(zr + 2), z3 = __ldg(zr + 3);
            float v = bd;
            v = fmaf(z0.x, w0.x, v); v = fmaf(z0.y, w0.y, v);
            v = fmaf(z0.z, w0.z, v); v = fmaf(z0.w, w0.w, v);
            v = fmaf(z1.x, w1.x, v); v = fmaf(z1.y, w1.y, v);
            v = fmaf(z1.z, w1.z, v); v = fmaf(z1.w, w1.w, v);
            v = fmaf(z2.x, w2.x, v); v = fmaf(z2.y, w2.y, v);
            v = fmaf(z2.z, w2.z, v); v = fmaf(z2.w, w2.w, v);
            v = fmaf(z3.x, w3.x, v); v = fmaf(z3.y, w3.y, v);
            v = fmaf(z3.z, w3.z, v); v = fmaf(z3.w, w3.w, v);
            out[X_OFF + (size_t)(rbase + rr) * FDIM + tid] = v;
        }
    } else {
        // ---- role J ----
        float4* tile = (float4*)smem;
        const float4* we4 = (const float4*)W_enc;
        for (int i = tid; i < 512; i += 128) tile[i] = we4[i];
        __syncthreads();
        const int jb = g * 5 + (r - 2);      // 0..1279
        jac_store(out, tile, JAC_F_BEG, JAC_F_LEN, jb, 1280, tid, 128);
    }
}

// ---------------------------------------------------------------------------
extern "C" void kernel_launch(void* const* d_in, const int* in_sizes, int n_in,
                              void* d_out, int out_size)
{
    const float* x       = (const float*)d_in[0];
    const float* W_enc   = (const float*)d_in[1];
    const float* b_enc   = (const float*)d_in[2];
    const float* W_dec   = (const float*)d_in[3];
    const float* b_dec   = (const float*)d_in[4];
    const float* W_sindy = (const float*)d_in[5];
    const float* b_sindy = (const float*)d_in[6];
    float* out = (float*)d_out;

    float* z_out = out + Z_OFF;

    encoder_kernel<<<769, 256>>>(x, W_enc, b_enc, W_sindy, z_out, out);
    hilbert_kernel<<<768, 512>>>(W_enc, out);
    fused_kernel<<<1793, 128, 128 * 49 * 4>>>(
        W_enc, W_dec, b_dec, W_sindy, b_sindy, z_out, out);
}

// round 8
// speedup vs baseline: 1.7921x; 1.7921x over previous
#include <cuda_runtime.h>
#include <math.h>

#define BDIM   16
#define TDIM   2048
#define FDIM   128
#define LDIM   16
#define LIB    1016
#define NROWS  (BDIM*TDIM)          // 32768

// output offsets (floats)
#define Y_OFF   ((size_t)0)
#define X_OFF   ((size_t)524288)
#define Z_OFF   ((size_t)4718592)
#define J_OFF   ((size_t)5242880)
#define WS_OFF  ((size_t)72351744)
#define WD_OFF  ((size_t)72368000)

// jac float4 region split:  encoder [0,2M) | hilbert [2M,6.29M) | fused [6.29M,16.77M)
#define JAC_E_BEG    ((size_t)0)
#define JAC_E_LEN    ((size_t)2097152)
#define JAC_H_BEG    ((size_t)2097152)
#define JAC_H_LEN    ((size_t)4194304)
#define JAC_F_BEG    ((size_t)6291456)
#define JAC_F_LEN    ((size_t)10485760)

// scratch
__device__ float g_amp[BDIM*LDIM*TDIM];          // [B,L,T]
__device__ float g_ang[BDIM*LDIM*TDIM];          // [B,L,T]
__device__ float g_zt [BDIM*LDIM*TDIM];          // [B,L,T]
__device__ __align__(16) float g_Wt[LIB*LDIM];   // W_sindy transposed [d][l]
__device__ unsigned int g_combo[LIB];            // packed (i | j<<8 | k<<16), idx into f[], 49 = 1.0

// fused smem layout (floats): [ Wt 16256 | f 128*52=6656 | combo 1016 ] = 23928 fl = 95712 B
#define SM_WT    0
#define SM_F     16256
#define SM_COMBO (16256 + 6656)
#define FUSED_SMEM_FLOATS (16256 + 6656 + 1016)

// ---------------------------------------------------------------------------
__device__ __forceinline__ void jac_store(float* __restrict__ out,
                                          const float4* __restrict__ tile,
                                          size_t region_beg, size_t region_len,
                                          int jb, int nblk, int tid, int nthr)
{
    float4* jac4 = (float4*)(out + J_OFF);
    const size_t stride = (size_t)nblk * nthr;
    for (size_t v = (size_t)jb * nthr + tid; v < region_len; v += stride) {
        size_t gidx = region_beg + v;
        __stcs(&jac4[gidx], tile[gidx & 511]);
    }
}

// ---------------------------------------------------------------------------
// K1: encoder. blocks [0,256): z = x @ W_enc^T + b_enc, 2 threads per row.
//     block 256: transpose W_sindy -> g_Wt and build combo table.
//     blocks [257,769): jac region E.
// ---------------------------------------------------------------------------
__global__ __launch_bounds__(256) void encoder_kernel(
    const float* __restrict__ x, const float* __restrict__ W_enc,
    const float* __restrict__ b_enc, const float* __restrict__ W_sindy,
    float* __restrict__ z_out, float* __restrict__ out)
{
    __shared__ float4 sW[512];
    __shared__ float  sb[16];
    const int tid = threadIdx.x;
    const int bb  = blockIdx.x;

    if (bb == 256) {
        // transpose W_sindy [16][1016] -> g_Wt [1016][16]
        for (int i = tid; i < LDIM * LIB; i += 256) {
            int l = i / LIB;
            int d = i - l * LIB;
            g_Wt[d * 16 + l] = W_sindy[i];
        }
        // combo table (reference feature order)
        if (tid < 16) {
            // degree-3 block for i = tid, base offset 152 + sum of earlier triangles
            int off = 152;
            for (int a = 0; a < tid; a++) { int n = 16 - a; off += n * (n + 1) / 2; }
            for (int j = tid; j < 16; j++)
                for (int k = j; k < 16; k++)
                    g_combo[off++] = (unsigned)tid | ((unsigned)j << 8) | ((unsigned)k << 16);
        } else if (tid == 16) {
            int d = 0;
            for (int i = 0; i < 16; i++)                       // degree 1
                g_combo[d++] = (unsigned)i | (49u << 8) | (49u << 16);
            for (int i = 0; i < 16; i++)                       // degree 2
                for (int j = i; j < 16; j++)
                    g_combo[d++] = (unsigned)i | ((unsigned)j << 8) | (49u << 16);
        } else if (tid == 17) {
            int d = 968;                                       // z, amp, ang tails
            for (int i = 0; i < 48; i++)
                g_combo[d++] = (unsigned)i | (49u << 8) | (49u << 16);
        }
        return;
    }

    for (int i = tid; i < 512; i += 256) sW[i] = ((const float4*)W_enc)[i];

    if (bb >= 257) {
        __syncthreads();
        jac_store(out, sW, JAC_E_BEG, JAC_E_LEN, bb - 257, 512, tid, 256);
        return;
    }

    if (tid < 16) sb[tid] = b_enc[tid];
    __syncthreads();

    const int gt   = bb * 256 + tid;
    const int row  = gt >> 1;
    const int half = gt & 1;
    const float4* xr = (const float4*)(x + (size_t)row * FDIM) + half * 16;

    float acc[16];
#pragma unroll
    for (int l = 0; l < 16; l++) acc[l] = 0.0f;

#pragma unroll
    for (int c = 0; c < 16; c++) {
        float4 xv = xr[c];
#pragma unroll
        for (int l = 0; l < 16; l++) {
            float4 wv = sW[l * 32 + half * 16 + c];
            acc[l] = fmaf(xv.x, wv.x, acc[l]);
            acc[l] = fmaf(xv.y, wv.y, acc[l]);
            acc[l] = fmaf(xv.z, wv.z, acc[l]);
            acc[l] = fmaf(xv.w, wv.w, acc[l]);
        }
    }
#pragma unroll
    for (int l = 0; l < 16; l++)
        acc[l] += __shfl_xor_sync(0xffffffffu, acc[l], 1);
#pragma unroll
    for (int l = 0; l < 16; l++) acc[l] += sb[l];

    float4* zo = (float4*)(z_out + (size_t)row * LDIM);
    if (half == 0) {
        zo[0] = make_float4(acc[0], acc[1], acc[2],  acc[3]);
        zo[1] = make_float4(acc[4], acc[5], acc[6],  acc[7]);
    } else {
        zo[2] = make_float4(acc[8],  acc[9],  acc[10], acc[11]);
        zo[3] = make_float4(acc[12], acc[13], acc[14], acc[15]);
    }
    const int b = row >> 11;
    const int t = row & 2047;
#pragma unroll
    for (int k = 0; k < 8; k++) {
        int l = half * 8 + k;
        g_zt[((size_t)(b * 16 + l)) * TDIM + t] = acc[l];
    }
}

// ---------------------------------------------------------------------------
// K2: hilbert. blocks [0,256): FFT->filter->iFFT per (b,lat) in [B,L,T].
//     blocks [256,768): jac region H.
// ---------------------------------------------------------------------------
__global__ __launch_bounds__(512) void hilbert_kernel(
    const float* __restrict__ W_enc, float* __restrict__ out)
{
    __shared__ float2 bufA[2048];
    __shared__ float2 bufB[2048];
    const int tid = threadIdx.x;
    const int bb  = blockIdx.x;

    if (bb >= 256) {
        float4* tile = (float4*)bufA;
        const float4* we4 = (const float4*)W_enc;
        if (tid < 512) tile[tid] = we4[tid];
        __syncthreads();
        jac_store(out, tile, JAC_H_BEG, JAC_H_LEN, bb - 256, 512, tid, 512);
        return;
    }

    const int seq = bb;
    const float* zp = g_zt + (size_t)seq * TDIM;
    for (int t = tid; t < 2048; t += 512)
        bufA[t] = make_float2(zp[t], 0.0f);
    __syncthreads();

    float2* src = bufA;
    float2* dst = bufB;

    for (int p = 0; p < 11; p++) {                 // forward FFT
        const int   len  = 1 << p;
        const float coef = -3.14159265358979323846f / (float)len;
        for (int j = tid; j < 1024; j += 512) {
            const int k = j & (len - 1);
            float2 a  = src[j];
            float2 b2 = src[j + 1024];
            float s, c;
            __sincosf(coef * (float)k, &s, &c);
            float2 wb = make_float2(c * b2.x - s * b2.y, c * b2.y + s * b2.x);
            const int base = 2 * (j - k) + k;
            dst[base]       = make_float2(a.x + wb.x, a.y + wb.y);
            dst[base + len] = make_float2(a.x - wb.x, a.y - wb.y);
        }
        __syncthreads();
        float2* tsw = src; src = dst; dst = tsw;
    }

    for (int t = tid; t < 2048; t += 512) {        // H filter
        float h = (t >= 1 && t < 1024) ? 2.0f : 0.0f;
        src[t].x *= h;
        src[t].y *= h;
    }
    __syncthreads();

    for (int p = 0; p < 11; p++) {                 // inverse FFT
        const int   len  = 1 << p;
        const float coef = 3.14159265358979323846f / (float)len;
        for (int j = tid; j < 1024; j += 512) {
            const int k = j & (len - 1);
            float2 a  = src[j];
            float2 b2 = src[j + 1024];
            float s, c;
            __sincosf(coef * (float)k, &s, &c);
            float2 wb = make_float2(c * b2.x - s * b2.y, c * b2.y + s * b2.x);
            const int base = 2 * (j - k) + k;
            dst[base]       = make_float2(a.x + wb.x, a.y + wb.y);
            dst[base + len] = make_float2(a.x - wb.x, a.y - wb.y);
        }
        __syncthreads();
        float2* tsw = src; src = dst; dst = tsw;
    }

    const float scale = 1.0f / 2048.0f;
    const size_t ob = (size_t)seq * TDIM;
    for (int t = tid; t < 2048; t += 512) {
        float re = src[t].x * scale;
        float im = src[t].y * scale;
        g_amp[ob + t] = sqrtf(re * re + im * im);
        g_ang[ob + t] = atan2f(im, re);
    }
}

// ---------------------------------------------------------------------------
// K3: fused, 256-thread blocks, period-7 interleave 1Y:1X:5J + 1 copy block.
//   Y: 128 rows/block, 2 threads/row (feature range split 508/508),
//      features via combo table, W_sindy^T in smem (broadcast reads).
//   X: x_hat, 2 half-row-ranges x 128 cols.
//   J: jac region F streaming stores.
// ---------------------------------------------------------------------------
__global__ __launch_bounds__(256) void fused_kernel(
    const float* __restrict__ W_enc,
    const float* __restrict__ W_dec,   const float* __restrict__ b_dec,
    const float* __restrict__ W_sindy, const float* __restrict__ b_sindy,
    const float* __restrict__ z,       // z region of output blob [B,T,L]
    float* __restrict__ out)
{
    extern __shared__ float smem[];
    const int tid = threadIdx.x;
    const int bb  = blockIdx.x;

    if (bb == 1792) {
        // ---- role C ----
        const float4* ws4 = (const float4*)W_sindy;
        float4* o1 = (float4*)(out + WS_OFF);
        for (int i = tid; i < (LDIM * LIB) / 4; i += 256) o1[i] = ws4[i];
        const float4* wd4 = (const float4*)W_dec;
        float4* o2 = (float4*)(out + WD_OFF);
        for (int i = tid; i < (FDIM * LDIM) / 4; i += 256) o2[i] = wd4[i];
        return;
    }

    const int g = bb / 7;
    const int r = bb - g * 7;

    if (r == 0) {
        // ---- role Y ----
        float* s_Wt = smem + SM_WT;
        float* s_f  = smem + SM_F;
        unsigned int* s_combo = (unsigned int*)(smem + SM_COMBO);

        // coalesced loads of transposed W and combo table
        {
            const float4* wt4 = (const float4*)g_Wt;
            float4* d4 = (float4*)s_Wt;
            for (int i = tid; i < (LIB * LDIM) / 4; i += 256) d4[i] = wt4[i];
            for (int i = tid; i < LIB; i += 256) s_combo[i] = g_combo[i];
        }

        const int row_local = tid >> 1;        // 0..127
        const int half      = tid & 1;
        const int row       = g * 128 + row_local;
        const int b         = row >> 11;
        const int t         = row & 2047;
        float* f = s_f + row_local * 52;

        if (half == 0) {
            const float4* zr4 = (const float4*)(z + (size_t)row * LDIM);
            float4 z0 = zr4[0], z1 = zr4[1], z2 = zr4[2], z3 = zr4[3];
            f[0]=z0.x;  f[1]=z0.y;  f[2]=z0.z;  f[3]=z0.w;
            f[4]=z1.x;  f[5]=z1.y;  f[6]=z1.z;  f[7]=z1.w;
            f[8]=z2.x;  f[9]=z2.y;  f[10]=z2.z; f[11]=z2.w;
            f[12]=z3.x; f[13]=z3.y; f[14]=z3.z; f[15]=z3.w;
            f[49] = 1.0f;
        } else {
#pragma unroll
            for (int i = 0; i < 16; i++) {
                f[16 + i] = g_amp[((size_t)(b * 16 + i)) * TDIM + t];
                f[32 + i] = g_ang[((size_t)(b * 16 + i)) * TDIM + t];
            }
        }
        __syncthreads();

        float acc[16];
#pragma unroll
        for (int l = 0; l < 16; l++) acc[l] = 0.0f;

        const int dlo = half * 508;
#pragma unroll 4
        for (int d = dlo; d < dlo + 508; d++) {
            unsigned int c = s_combo[d];
            float v = f[c & 63u] * f[(c >> 8) & 63u] * f[(c >> 16) & 63u];
            const float4* w4 = (const float4*)(s_Wt + (d << 4));
            float4 w0 = w4[0], w1 = w4[1], w2 = w4[2], w3 = w4[3];
            acc[0]  = fmaf(v, w0.x, acc[0]);  acc[1]  = fmaf(v, w0.y, acc[1]);
            acc[2]  = fmaf(v, w0.z, acc[2]);  acc[3]  = fmaf(v, w0.w, acc[3]);
            acc[4]  = fmaf(v, w1.x, acc[4]);  acc[5]  = fmaf(v, w1.y, acc[5]);
            acc[6]  = fmaf(v, w1.z, acc[6]);  acc[7]  = fmaf(v, w1.w, acc[7]);
            acc[8]  = fmaf(v, w2.x, acc[8]);  acc[9]  = fmaf(v, w2.y, acc[9]);
            acc[10] = fmaf(v, w2.z, acc[10]); acc[11] = fmaf(v, w2.w, acc[11]);
            acc[12] = fmaf(v, w3.x, acc[12]); acc[13] = fmaf(v, w3.y, acc[13]);
            acc[14] = fmaf(v, w3.z, acc[14]); acc[15] = fmaf(v, w3.w, acc[15]);
        }
#pragma unroll
        for (int l = 0; l < 16; l++)
            acc[l] += __shfl_xor_sync(0xffffffffu, acc[l], 1);

        // half 0 stores outputs 0..7, half 1 stores 8..15 (each +bias)
        const float* bs = b_sindy + half * 8;
        const int o = half * 8;
        float4 oA = make_float4(acc[o+0] + bs[0], acc[o+1] + bs[1],
                                acc[o+2] + bs[2], acc[o+3] + bs[3]);
        float4 oB = make_float4(acc[o+4] + bs[4], acc[o+5] + bs[5],
                                acc[o+6] + bs[6], acc[o+7] + bs[7]);
        float4* yo = (float4*)(out + Y_OFF + (size_t)row * LDIM) + half * 2;
        yo[0] = oA; yo[1] = oB;
    } else if (r == 1) {
        // ---- role X ----
        const int col   = tid & 127;
        const int rhalf = tid >> 7;
        const float4* wd = (const float4*)W_dec;
        float4 w0 = wd[col * 4 + 0];
        float4 w1 = wd[col * 4 + 1];
        float4 w2 = wd[col * 4 + 2];
        float4 w3 = wd[col * 4 + 3];
        float  bd = b_dec[col];
        const int rbase = g * 128 + rhalf * 64;
#pragma unroll 4
        for (int rr = 0; rr < 64; rr++) {
            const float4* zr = (const float4*)(z + (size_t)(rbase + rr) * LDIM);
            float4 z0 = __ldg(zr + 0), z1 = __ldg(zr + 1);
            float4 z2 = __ldg(zr + 2), z3 = __ldg(zr + 3);
            float v = bd;
            v = fmaf(z0.x, w0.x, v); v = fmaf(z0.y, w0.y, v);
            v = fmaf(z0.z, w0.z, v); v = fmaf(z0.w, w0.w, v);
            v = fmaf(z1.x, w1.x, v); v = fmaf(z1.y, w1.y, v);
            v = fmaf(z1.z, w1.z, v); v = fmaf(z1.w, w1.w, v);
            v = fmaf(z2.x, w2.x, v); v = fmaf(z2.y, w2.y, v);
            v = fmaf(z2.z, w2.z, v); v = fmaf(z2.w, w2.w, v);
            v = fmaf(z3.x, w3.x, v); v = fmaf(z3.y, w3.y, v);
            v = fmaf(z3.z, w3.z, v); v = fmaf(z3.w, w3.w, v);
            out[X_OFF + (size_t)(rbase + rr) * FDIM + col] = v;
        }
    } else {
        // ---- role J ----
        float4* tile = (float4*)smem;
        const float4* we4 = (const float4*)W_enc;
        for (int i = tid; i < 512; i += 256) tile[i] = we4[i];
        __syncthreads();
        const int jb = g * 5 + (r - 2);      // 0..1279
        jac_store(out, tile, JAC_F_BEG, JAC_F_LEN, jb, 1280, tid, 256);
    }
}

// ---------------------------------------------------------------------------
extern "C" void kernel_launch(void* const* d_in, const int* in_sizes, int n_in,
                              void* d_out, int out_size)
{
    const float* x       = (const float*)d_in[0];
    const float* W_enc   = (const float*)d_in[1];
    const float* b_enc   = (const float*)d_in[2];
    const float* W_dec   = (const float*)d_in[3];
    const float* b_dec   = (const float*)d_in[4];
    const float* W_sindy = (const float*)d_in[5];
    const float* b_sindy = (const float*)d_in[6];
    float* out = (float*)d_out;

    float* z_out = out + Z_OFF;

    encoder_kernel<<<769, 256>>>(x, W_enc, b_enc, W_sindy, z_out, out);
    hilbert_kernel<<<768, 512>>>(W_enc, out);

    static int smem_set = 0;
    if (!smem_set) {
        cudaFuncSetAttribute(fused_kernel,
                             cudaFuncAttributeMaxDynamicSharedMemorySize,
                             FUSED_SMEM_FLOATS * 4);
        smem_set = 1;
    }
    fused_kernel<<<1793, 256, FUSED_SMEM_FLOATS * 4>>>(
        W_enc, W_dec, b_dec, W_sindy, b_sindy, z_out, out);
}